// round 9
// baseline (speedup 1.0000x reference)
#include <cuda_runtime.h>
#include <math.h>
#include <stdint.h>

#define KDIM     4096
#define NJ       24             // 4 pre + 4 post + 16 res
#define MM       256            // rows per CTA
#define BLOCK    256            // 8 warps
#define KC       32             // k per chunk (128 B per row)
#define NC       (KDIM / KC)    // 128 chunks
#define XSTR     36             // floats per staged row (stride 144 B, conflict-free frags)
#define STAGEF   ((MM + NJ) * XSTR)        // floats per stage = 10080
#define WOFF     (MM * XSTR)               // weights offset inside stage (floats)
#define NSTG     5
#define SMEM_BYTES (NSTG * STAGEF * 4)     // 201600 B
#define CHUNK_BYTES ((MM + NJ) * 128)      // 35840 B per-stage expected tx
#define SDSTR    28             // epilogue transpose stride
#define RMS_EPS  1.1920928955078125e-07f
#define SK_EPS   1e-6f

__device__ __align__(16) float g_Wt[NJ * KDIM];   // j-major, k contiguous, pre-scaled

// ---------------- helpers ----------------
__device__ __forceinline__ uint32_t smem_u32(const void* p) {
    return (uint32_t)__cvta_generic_to_shared(p);
}
// 1D bulk copy gmem -> smem with mbarrier transaction tracking (sm_90 baseline)
__device__ __forceinline__ void bulk_g2s(uint32_t dst, const void* src,
                                         uint32_t bytes, uint32_t mbar) {
    asm volatile("cp.async.bulk.shared::cluster.global.mbarrier::complete_tx::bytes "
                 "[%0], [%1], %2, [%3];"
                 :: "r"(dst), "l"(src), "r"(bytes), "r"(mbar) : "memory");
}
#define MBARRIER_INIT(addr, cnt) \
    asm volatile("mbarrier.init.shared.b64 [%0], %1;" :: "r"(addr), "r"(cnt) : "memory")
#define MBARRIER_EXPECT_TX(addr, bytes) \
    asm volatile("mbarrier.arrive.expect_tx.shared.b64 _, [%0], %1;" \
                 :: "r"(addr), "r"(bytes) : "memory")
#define MBARRIER_WAIT_PARITY(addr, par) do { \
    uint32_t _m = (addr); uint32_t _p = (par); \
    asm volatile("{\n\t.reg .pred P1;\n\t" \
        "WL%=:\n\t" \
        "mbarrier.try_wait.parity.acquire.cta.shared::cta.b64 P1, [%0], %1, 0x989680;\n\t" \
        "@P1 bra.uni WD%=;\n\t" \
        "bra.uni WL%=;\n\t" \
        "WD%=:\n\t}" :: "r"(_m), "r"(_p) : "memory"); \
} while (0)

__device__ __forceinline__ void mma_tf32(float d[4],
                                         uint32_t a0, uint32_t a1, uint32_t a2, uint32_t a3,
                                         uint32_t b0, uint32_t b1) {
    asm volatile("mma.sync.aligned.m16n8k8.row.col.f32.tf32.tf32.f32 "
                 "{%0,%1,%2,%3}, {%4,%5,%6,%7}, {%8,%9}, {%0,%1,%2,%3};"
                 : "+f"(d[0]), "+f"(d[1]), "+f"(d[2]), "+f"(d[3])
                 : "r"(a0), "r"(a1), "r"(a2), "r"(a3), "r"(b0), "r"(b1));
}
__device__ __forceinline__ uint32_t f2u(float f) { return __float_as_uint(f); }

__global__ void prep_kernel(const float* __restrict__ norm_w,
                            const float* __restrict__ W_pre,
                            const float* __restrict__ W_post,
                            const float* __restrict__ W_res,
                            const float* __restrict__ a_pre,
                            const float* __restrict__ a_post,
                            const float* __restrict__ a_res) {
    int idx = blockIdx.x * blockDim.x + threadIdx.x;
    if (idx >= NJ * KDIM) return;
    int j = idx / KDIM;
    int k = idx - j * KDIM;
    float w, a;
    if (j < 4)      { w = W_pre [j * KDIM + k];       a = a_pre[0];  }
    else if (j < 8) { w = W_post[(j - 4) * KDIM + k]; a = a_post[0]; }
    else            { w = W_res [(j - 8) * KDIM + k]; a = a_res[0];  }
    g_Wt[j * KDIM + k] = w * a * norm_w[k];
}

__global__ __launch_bounds__(BLOCK, 1)
void mhc_mma_kernel(const float* __restrict__ x,
                    const float* __restrict__ b_pre,
                    const float* __restrict__ b_post,
                    const float* __restrict__ b_res,
                    float* __restrict__ out, int Btot) {
    extern __shared__ float dsm[];
    __shared__ float ssqp[BLOCK];
    __shared__ __align__(8) uint64_t mbars[NSTG];

    const int tid  = threadIdx.x;
    const int lane = tid & 31;
    const int warp = tid >> 5;
    const int g    = lane >> 2;       // groupID
    const int c4   = lane & 3;        // threadID_in_group
    const int rowbase = blockIdx.x * MM;

    if (tid == 0) {
#pragma unroll
        for (int s = 0; s < NSTG; s++) MBARRIER_INIT(smem_u32(&mbars[s]), 1);
    }
    __syncthreads();

    // ---- bulk chunk loader: thread t copies row t (128 B); threads 0..23 also copy W rows
    const float* xrow = x + (size_t)rowbase * KDIM;
    const uint32_t sbase = smem_u32(dsm);
    auto issue_chunk = [&](int c) {
        const int s = c % NSTG;
        const uint32_t ab = sbase + s * (STAGEF * 4);
        const uint32_t mb = smem_u32(&mbars[s]);
        if (tid == 0) MBARRIER_EXPECT_TX(mb, CHUNK_BYTES);
        bulk_g2s(ab + tid * (XSTR * 4),
                 xrow + (size_t)tid * KDIM + c * KC, 128, mb);
        if (tid < NJ)
            bulk_g2s(ab + WOFF * 4 + tid * (XSTR * 4),
                     g_Wt + (size_t)tid * KDIM + c * KC, 128, mb);
    };

    issue_chunk(0); issue_chunk(1); issue_chunk(2); issue_chunk(3);

    // D accumulators: [mtile][ntile][4]  (2 m16 tiles per warp, 3 n8 tiles)
    float d[2][3][4];
#pragma unroll
    for (int mt = 0; mt < 2; mt++)
#pragma unroll
        for (int n = 0; n < 3; n++)
#pragma unroll
            for (int q = 0; q < 4; q++) d[mt][n][q] = 0.0f;

    // per-thread fragment offsets (floats, within stage)
    const int m0 = warp * 32;
    const int aof0 = (m0 + g) * XSTR + c4;            // tile0 row g
    const int aof1 = aof0 + 8 * XSTR;                 // tile0 row g+8
    const int aof2 = aof0 + 16 * XSTR;                // tile1 row g
    const int aof3 = aof0 + 24 * XSTR;                // tile1 row g+8
    const int bof0 = WOFF + (0 + g) * XSTR + c4;
    const int bof1 = WOFF + (8 + g) * XSTR + c4;
    const int bof2 = WOFF + (16 + g) * XSTR + c4;

    float ssq = 0.0f;

    for (int c = 0; c < NC; ++c) {
        const int s = c % NSTG;
        MBARRIER_WAIT_PARITY(smem_u32(&mbars[s]), ((c / NSTG) & 1));

        const float* fs = dsm + s * STAGEF;

        // ssq: thread owns row tid (exact fp32)
        {
            const float4* xr = (const float4*)(fs + tid * XSTR);
#pragma unroll
            for (int i = 0; i < 8; i++) {
                float4 v = xr[i];
                ssq += v.x * v.x + v.y * v.y + v.z * v.z + v.w * v.w;
            }
        }

        // MMA: 4 k8-steps, 2 m-tiles x 3 n-tiles
#pragma unroll
        for (int ks = 0; ks < 4; ks++) {
            const int k0 = ks * 8;
            uint32_t A0[4], A1[4];
            A0[0] = f2u(fs[aof0 + k0]);     A0[1] = f2u(fs[aof1 + k0]);
            A0[2] = f2u(fs[aof0 + k0 + 4]); A0[3] = f2u(fs[aof1 + k0 + 4]);
            A1[0] = f2u(fs[aof2 + k0]);     A1[1] = f2u(fs[aof3 + k0]);
            A1[2] = f2u(fs[aof2 + k0 + 4]); A1[3] = f2u(fs[aof3 + k0 + 4]);
            uint32_t b0, b1;
            b0 = f2u(fs[bof0 + k0]); b1 = f2u(fs[bof0 + k0 + 4]);
            mma_tf32(d[0][0], A0[0], A0[1], A0[2], A0[3], b0, b1);
            mma_tf32(d[1][0], A1[0], A1[1], A1[2], A1[3], b0, b1);
            b0 = f2u(fs[bof1 + k0]); b1 = f2u(fs[bof1 + k0 + 4]);
            mma_tf32(d[0][1], A0[0], A0[1], A0[2], A0[3], b0, b1);
            mma_tf32(d[1][1], A1[0], A1[1], A1[2], A1[3], b0, b1);
            b0 = f2u(fs[bof2 + k0]); b1 = f2u(fs[bof2 + k0 + 4]);
            mma_tf32(d[0][2], A0[0], A0[1], A0[2], A0[3], b0, b1);
            mma_tf32(d[1][2], A1[0], A1[1], A1[2], A1[3], b0, b1);
        }

        __syncthreads();                          // all reads of chunk c (and c-1) done
        if (c + 4 < NC) issue_chunk(c + 4);       // overwrites buffer of chunk c-1
    }

    ssqp[tid] = ssq;
    __syncthreads();                              // reuse dsm for sD

    // transpose D through smem: sD[row][j], stride 28
    float* sD = dsm;
#pragma unroll
    for (int mt = 0; mt < 2; mt++) {
        const int r0 = m0 + mt * 16 + g;
#pragma unroll
        for (int n = 0; n < 3; n++) {
            *(float2*)&sD[r0 * SDSTR + 8 * n + 2 * c4] =
                make_float2(d[mt][n][0], d[mt][n][1]);
            *(float2*)&sD[(r0 + 8) * SDSTR + 8 * n + 2 * c4] =
                make_float2(d[mt][n][2], d[mt][n][3]);
        }
    }
    __syncthreads();

    // epilogue: one row per thread
    {
        const int row = rowbase + tid;
        const float* a = &sD[tid * SDSTR];
        const float rinv = rsqrtf(ssqp[tid] * (1.0f / (float)KDIM) + RMS_EPS);

        float4 o;
        {
            float p0 = rinv * a[0] + b_pre[0];
            float p1 = rinv * a[1] + b_pre[1];
            float p2 = rinv * a[2] + b_pre[2];
            float p3 = rinv * a[3] + b_pre[3];
            o.x = __fdividef(1.0f, 1.0f + __expf(-p0));
            o.y = __fdividef(1.0f, 1.0f + __expf(-p1));
            o.z = __fdividef(1.0f, 1.0f + __expf(-p2));
            o.w = __fdividef(1.0f, 1.0f + __expf(-p3));
            *(float4*)(out + (size_t)row * 4) = o;
        }
        {
            float p0 = rinv * a[4] + b_post[0];
            float p1 = rinv * a[5] + b_post[1];
            float p2 = rinv * a[6] + b_post[2];
            float p3 = rinv * a[7] + b_post[3];
            o.x = 2.0f * __fdividef(1.0f, 1.0f + __expf(-p0));
            o.y = 2.0f * __fdividef(1.0f, 1.0f + __expf(-p1));
            o.z = 2.0f * __fdividef(1.0f, 1.0f + __expf(-p2));
            o.w = 2.0f * __fdividef(1.0f, 1.0f + __expf(-p3));
            *(float4*)(out + (size_t)Btot * 4 + (size_t)row * 4) = o;
        }

        float M[16];
#pragma unroll
        for (int j = 0; j < 16; j++)
            M[j] = __expf(rinv * a[8 + j] + b_res[j]);
#pragma unroll 1
        for (int it = 0; it < 20; it++) {
#pragma unroll
            for (int r = 0; r < 4; r++) {
                float sv = M[4*r] + M[4*r+1] + M[4*r+2] + M[4*r+3] + SK_EPS;
                float inv = __fdividef(1.0f, sv);
                M[4*r] *= inv; M[4*r+1] *= inv; M[4*r+2] *= inv; M[4*r+3] *= inv;
            }
#pragma unroll
            for (int cq = 0; cq < 4; cq++) {
                float sv = M[cq] + M[cq+4] + M[cq+8] + M[cq+12] + SK_EPS;
                float inv = __fdividef(1.0f, sv);
                M[cq] *= inv; M[cq+4] *= inv; M[cq+8] *= inv; M[cq+12] *= inv;
            }
        }
        float* ro = out + (size_t)Btot * 8 + (size_t)row * 16;
#pragma unroll
        for (int q = 0; q < 4; q++) {
            o.x = M[4*q]; o.y = M[4*q+1]; o.z = M[4*q+2]; o.w = M[4*q+3];
            *(float4*)(ro + 4 * q) = o;
        }
    }
}

extern "C" void kernel_launch(void* const* d_in, const int* in_sizes, int n_in,
                              void* d_out, int out_size) {
    const float* x      = (const float*)d_in[0];
    const float* norm_w = (const float*)d_in[1];
    const float* W_pre  = (const float*)d_in[2];
    const float* W_post = (const float*)d_in[3];
    const float* W_res  = (const float*)d_in[4];
    const float* b_pre  = (const float*)d_in[5];
    const float* b_post = (const float*)d_in[6];
    const float* b_res  = (const float*)d_in[7];
    const float* a_pre  = (const float*)d_in[8];
    const float* a_post = (const float*)d_in[9];
    const float* a_res  = (const float*)d_in[10];

    const int Btot = in_sizes[0] / KDIM;

    cudaFuncSetAttribute(mhc_mma_kernel,
                         cudaFuncAttributeMaxDynamicSharedMemorySize,
                         SMEM_BYTES);

    prep_kernel<<<(NJ * KDIM + 255) / 256, 256>>>(norm_w, W_pre, W_post, W_res,
                                                  a_pre, a_post, a_res);
    mhc_mma_kernel<<<Btot / MM, BLOCK, SMEM_BYTES>>>(x, b_pre, b_post, b_res,
                                                     (float*)d_out, Btot);
}

// round 10
// speedup vs baseline: 1.3663x; 1.3663x over previous
#include <cuda_runtime.h>
#include <math.h>
#include <stdint.h>

#define KDIM     4096
#define NJ       24             // 4 pre + 4 post + 16 res
#define MM       256            // rows per CTA
#define BLOCK    256            // 8 warps, warp w owns rows w*32..w*32+31
#define KC       32             // k per chunk (128 B per row)
#define NC       (KDIM / KC)    // 128 chunks
#define XSTR     36             // floats per staged row (stride 144 B)
#define WBUF     (32 * XSTR)    // per-warp per-stage floats = 1152
#define NSTG     5
#define SMEM_BYTES (8 * NSTG * WBUF * 4)   // 184320 B
#define SDSTR    28             // epilogue transpose stride
#define RMS_EPS  1.1920928955078125e-07f
#define SK_EPS   1e-6f

__device__ __align__(16) float g_Wt[NJ * KDIM];   // j-major, k contiguous, pre-scaled

// ---------------- helpers ----------------
__device__ __forceinline__ uint32_t smem_u32(const void* p) {
    return (uint32_t)__cvta_generic_to_shared(p);
}
__device__ __forceinline__ void cp16cg(uint32_t dst, const void* src) {
    asm volatile("cp.async.cg.shared.global [%0], [%1], 16;" :: "r"(dst), "l"(src));
}
__device__ __forceinline__ void cp_commit() { asm volatile("cp.async.commit_group;"); }
template <int N> __device__ __forceinline__ void cp_wait() {
    asm volatile("cp.async.wait_group %0;" :: "n"(N));
}
__device__ __forceinline__ void mma_tf32(float d[4],
                                         uint32_t a0, uint32_t a1, uint32_t a2, uint32_t a3,
                                         uint32_t b0, uint32_t b1) {
    asm volatile("mma.sync.aligned.m16n8k8.row.col.f32.tf32.tf32.f32 "
                 "{%0,%1,%2,%3}, {%4,%5,%6,%7}, {%8,%9}, {%0,%1,%2,%3};"
                 : "+f"(d[0]), "+f"(d[1]), "+f"(d[2]), "+f"(d[3])
                 : "r"(a0), "r"(a1), "r"(a2), "r"(a3), "r"(b0), "r"(b1));
}
__device__ __forceinline__ uint32_t f2u(float f) { return __float_as_uint(f); }

__global__ void prep_kernel(const float* __restrict__ norm_w,
                            const float* __restrict__ W_pre,
                            const float* __restrict__ W_post,
                            const float* __restrict__ W_res,
                            const float* __restrict__ a_pre,
                            const float* __restrict__ a_post,
                            const float* __restrict__ a_res) {
    int idx = blockIdx.x * blockDim.x + threadIdx.x;
    if (idx >= NJ * KDIM) return;
    int j = idx / KDIM;
    int k = idx - j * KDIM;
    float w, a;
    if (j < 4)      { w = W_pre [j * KDIM + k];       a = a_pre[0];  }
    else if (j < 8) { w = W_post[(j - 4) * KDIM + k]; a = a_post[0]; }
    else            { w = W_res [(j - 8) * KDIM + k]; a = a_res[0];  }
    g_Wt[j * KDIM + k] = w * a * norm_w[k];
}

__global__ __launch_bounds__(BLOCK, 1)
void mhc_mma_kernel(const float* __restrict__ x,
                    const float* __restrict__ b_pre,
                    const float* __restrict__ b_post,
                    const float* __restrict__ b_res,
                    float* __restrict__ out, int Btot) {
    extern __shared__ float dsm[];
    __shared__ float ssqp[BLOCK];

    const int tid  = threadIdx.x;
    const int lane = tid & 31;
    const int warp = tid >> 5;
    const int g    = lane >> 2;       // groupID
    const int c4   = lane & 3;        // threadID_in_group
    const int rowbase = blockIdx.x * MM;
    const int m0 = warp * 32;         // warp-private row slab

    // warp-private staging ring: dsm[warp][stage][32 rows][XSTR]
    float* wbuf = dsm + warp * (NSTG * WBUF);
    const uint32_t wb32 = smem_u32(wbuf);

    // ---- per-warp chunk loader (8 cp16 per lane) ----
    const float* xslab = x + (size_t)(rowbase + m0) * KDIM;
    auto issue_chunk = [&](int c) {
        const int s = c % NSTG;
        const uint32_t ab = wb32 + s * (WBUF * 4);
        const float* xb = xslab + c * KC;
#pragma unroll
        for (int i = 0; i < 8; i++) {            // 256 cp16 per warp
            int idx = i * 32 + lane;
            int r = idx >> 3, u = idx & 7;
            cp16cg(ab + r * (XSTR * 4) + u * 16,
                   xb + (size_t)r * KDIM + u * 4);
        }
        cp_commit();
    };

    issue_chunk(0); issue_chunk(1); issue_chunk(2); issue_chunk(3);

    // D accumulators: [mtile][ntile][4]
    float d[2][3][4];
#pragma unroll
    for (int mt = 0; mt < 2; mt++)
#pragma unroll
        for (int n = 0; n < 3; n++)
#pragma unroll
            for (int q = 0; q < 4; q++) d[mt][n][q] = 0.0f;

    // A fragment offsets within a stage (floats)
    const int aof0 = g * XSTR + c4;                   // tile0 row g
    const int aof1 = aof0 + 8 * XSTR;                 // tile0 row g+8
    const int aof2 = aof0 + 16 * XSTR;                // tile1 row g
    const int aof3 = aof0 + 24 * XSTR;                // tile1 row g+8

    // B fragment global pointers (j-major W, L1/L2-resident)
    const float* w0 = g_Wt + (size_t)(0  + g) * KDIM + c4;
    const float* w1 = g_Wt + (size_t)(8  + g) * KDIM + c4;
    const float* w2 = g_Wt + (size_t)(16 + g) * KDIM + c4;

    float ssq = 0.0f;

    for (int c = 0; c < NC; ++c) {
        const int rem = NC - 1 - c;
        if (rem >= 3) cp_wait<3>();
        else if (rem == 2) cp_wait<2>();
        else if (rem == 1) cp_wait<1>();
        else cp_wait<0>();
        // NO __syncthreads: buffer is warp-private, this warp consumed stage c-1 already

        const float* fs = wbuf + (c % NSTG) * WBUF;
        const int kg = c * KC;

        // ssq: lane owns row lane of the slab (exact fp32)
        {
            const float4* xr = (const float4*)(fs + lane * XSTR);
#pragma unroll
            for (int i = 0; i < 8; i++) {
                float4 v = xr[i];
                ssq += v.x * v.x + v.y * v.y + v.z * v.z + v.w * v.w;
            }
        }

        // MMA: 4 k8-steps, 2 m-tiles x 3 n-tiles; B from global (L1-hit)
#pragma unroll
        for (int ks = 0; ks < 4; ks++) {
            const int k0 = ks * 8;
            uint32_t A0[4], A1[4];
            A0[0] = f2u(fs[aof0 + k0]);     A0[1] = f2u(fs[aof1 + k0]);
            A0[2] = f2u(fs[aof0 + k0 + 4]); A0[3] = f2u(fs[aof1 + k0 + 4]);
            A1[0] = f2u(fs[aof2 + k0]);     A1[1] = f2u(fs[aof3 + k0]);
            A1[2] = f2u(fs[aof2 + k0 + 4]); A1[3] = f2u(fs[aof3 + k0 + 4]);
            uint32_t b0, b1;
            b0 = f2u(__ldg(w0 + kg + k0)); b1 = f2u(__ldg(w0 + kg + k0 + 4));
            mma_tf32(d[0][0], A0[0], A0[1], A0[2], A0[3], b0, b1);
            mma_tf32(d[1][0], A1[0], A1[1], A1[2], A1[3], b0, b1);
            b0 = f2u(__ldg(w1 + kg + k0)); b1 = f2u(__ldg(w1 + kg + k0 + 4));
            mma_tf32(d[0][1], A0[0], A0[1], A0[2], A0[3], b0, b1);
            mma_tf32(d[1][1], A1[0], A1[1], A1[2], A1[3], b0, b1);
            b0 = f2u(__ldg(w2 + kg + k0)); b1 = f2u(__ldg(w2 + kg + k0 + 4));
            mma_tf32(d[0][2], A0[0], A0[1], A0[2], A0[3], b0, b1);
            mma_tf32(d[1][2], A1[0], A1[1], A1[2], A1[3], b0, b1);
        }

        if (c + 4 < NC) issue_chunk(c + 4);       // reuses this warp's stage of chunk c-1
    }

    ssqp[tid] = ssq;                              // tid == row (warp*32+lane)
    __syncthreads();                              // all warps done -> reuse dsm for sD

    // transpose D through smem: sD[row][j], stride 28
    float* sD = dsm;
#pragma unroll
    for (int mt = 0; mt < 2; mt++) {
        const int r0 = m0 + mt * 16 + g;
#pragma unroll
        for (int n = 0; n < 3; n++) {
            *(float2*)&sD[r0 * SDSTR + 8 * n + 2 * c4] =
                make_float2(d[mt][n][0], d[mt][n][1]);
            *(float2*)&sD[(r0 + 8) * SDSTR + 8 * n + 2 * c4] =
                make_float2(d[mt][n][2], d[mt][n][3]);
        }
    }
    __syncthreads();

    // epilogue: one row per thread
    {
        const int row = rowbase + tid;
        const float* a = &sD[tid * SDSTR];
        const float rinv = rsqrtf(ssqp[tid] * (1.0f / (float)KDIM) + RMS_EPS);

        float4 o;
        {
            float p0 = rinv * a[0] + b_pre[0];
            float p1 = rinv * a[1] + b_pre[1];
            float p2 = rinv * a[2] + b_pre[2];
            float p3 = rinv * a[3] + b_pre[3];
            o.x = __fdividef(1.0f, 1.0f + __expf(-p0));
            o.y = __fdividef(1.0f, 1.0f + __expf(-p1));
            o.z = __fdividef(1.0f, 1.0f + __expf(-p2));
            o.w = __fdividef(1.0f, 1.0f + __expf(-p3));
            *(float4*)(out + (size_t)row * 4) = o;
        }
        {
            float p0 = rinv * a[4] + b_post[0];
            float p1 = rinv * a[5] + b_post[1];
            float p2 = rinv * a[6] + b_post[2];
            float p3 = rinv * a[7] + b_post[3];
            o.x = 2.0f * __fdividef(1.0f, 1.0f + __expf(-p0));
            o.y = 2.0f * __fdividef(1.0f, 1.0f + __expf(-p1));
            o.z = 2.0f * __fdividef(1.0f, 1.0f + __expf(-p2));
            o.w = 2.0f * __fdividef(1.0f, 1.0f + __expf(-p3));
            *(float4*)(out + (size_t)Btot * 4 + (size_t)row * 4) = o;
        }

        float M[16];
#pragma unroll
        for (int j = 0; j < 16; j++)
            M[j] = __expf(rinv * a[8 + j] + b_res[j]);
#pragma unroll 1
        for (int it = 0; it < 20; it++) {
#pragma unroll
            for (int r = 0; r < 4; r++) {
                float sv = M[4*r] + M[4*r+1] + M[4*r+2] + M[4*r+3] + SK_EPS;
                float inv = __fdividef(1.0f, sv);
                M[4*r] *= inv; M[4*r+1] *= inv; M[4*r+2] *= inv; M[4*r+3] *= inv;
            }
#pragma unroll
            for (int cq = 0; cq < 4; cq++) {
                float sv = M[cq] + M[cq+4] + M[cq+8] + M[cq+12] + SK_EPS;
                float inv = __fdividef(1.0f, sv);
                M[cq] *= inv; M[cq+4] *= inv; M[cq+8] *= inv; M[cq+12] *= inv;
            }
        }
        float* ro = out + (size_t)Btot * 8 + (size_t)row * 16;
#pragma unroll
        for (int q = 0; q < 4; q++) {
            o.x = M[4*q]; o.y = M[4*q+1]; o.z = M[4*q+2]; o.w = M[4*q+3];
            *(float4*)(ro + 4 * q) = o;
        }
    }
}

extern "C" void kernel_launch(void* const* d_in, const int* in_sizes, int n_in,
                              void* d_out, int out_size) {
    const float* x      = (const float*)d_in[0];
    const float* norm_w = (const float*)d_in[1];
    const float* W_pre  = (const float*)d_in[2];
    const float* W_post = (const float*)d_in[3];
    const float* W_res  = (const float*)d_in[4];
    const float* b_pre  = (const float*)d_in[5];
    const float* b_post = (const float*)d_in[6];
    const float* b_res  = (const float*)d_in[7];
    const float* a_pre  = (const float*)d_in[8];
    const float* a_post = (const float*)d_in[9];
    const float* a_res  = (const float*)d_in[10];

    const int Btot = in_sizes[0] / KDIM;

    cudaFuncSetAttribute(mhc_mma_kernel,
                         cudaFuncAttributeMaxDynamicSharedMemorySize,
                         SMEM_BYTES);

    prep_kernel<<<(NJ * KDIM + 255) / 256, 256>>>(norm_w, W_pre, W_post, W_res,
                                                  a_pre, a_post, a_res);
    mhc_mma_kernel<<<Btot / MM, BLOCK, SMEM_BYTES>>>(x, b_pre, b_post, b_res,
                                                     (float*)d_out, Btot);
}